// round 16
// baseline (speedup 1.0000x reference)
#include <cuda_runtime.h>
#include <cuda_fp16.h>
#include <cstdint>
#include <math.h>

#define NN 50000
#define EE 800000
#define NE 850000      // EE + NN self loops
#define D1 256         // H*DH = H*DOUT paths both 256 wide

#define SCAN_CH 256
#define SCAN_NB ((NN + SCAN_CH - 1) / SCAN_CH)   // 196

// ---------------- scratch (device globals; no allocation allowed) ----------
__device__ int    g_is64;
__device__ int    g_src[NE];
__device__ int    g_dst[NE];
__device__ int    g_srcp[NE];    // CSR (dst-grouped) order
__device__ int    g_deg[NN];
__device__ int    g_off[NN + 1];
__device__ int    g_cur[NN];
__device__ int    g_bsum[SCAN_NB];
__device__ __half g_xh [(size_t)NN * 128];  // fp16 input features (GEMM1 A)
__device__ __half g_hh [(size_t)NN * D1];   // fp16 hidden state (GEMM2 A)
__device__ __half g_xlh[(size_t)NN * D1];   // fp16 source transform (gathered)
__device__ float  g_xr [(size_t)NN * D1];   // fp32 target transform
__device__ __half g_w1l[128 * D1];          // transposed fp16 weights [n][k]
__device__ __half g_w1r[128 * D1];
__device__ __half g_w2l[D1 * D1];
__device__ __half g_w2r[D1 * D1];

struct h4 { __half2 lo, hi; };   // 4 halfs = 8 bytes

// host-side side stream + events, created once at load (no device memory)
struct AuxStreams {
    cudaStream_t s2;
    cudaEvent_t  e_fork, e_join;
    AuxStreams() {
        cudaStreamCreateWithFlags(&s2, cudaStreamNonBlocking);
        cudaEventCreateWithFlags(&e_fork, cudaEventDisableTiming);
        cudaEventCreateWithFlags(&e_join, cudaEventDisableTiming);
    }
};
static AuxStreams g_aux;

// ---------------- fp16 converts: x and transposed weights ------------------
__global__ void k_xh(const float4* __restrict__ x, uint2* __restrict__ xh,
                     int n4) {
    int i = blockIdx.x * blockDim.x + threadIdx.x;
    if (i >= n4) return;
    float4 v = x[i];
    __half2 lo = __floats2half2_rn(v.x, v.y);
    __half2 hi = __floats2half2_rn(v.z, v.w);
    xh[i] = make_uint2(*(unsigned*)&lo, *(unsigned*)&hi);
}

__global__ void k_wt(const float* __restrict__ W, __half* __restrict__ Wt,
                     int M, int Kc) {
    int i = blockIdx.x * blockDim.x + threadIdx.x;
    if (i >= M * Kc) return;
    int k = i / Kc, n = i % Kc;
    Wt[(size_t)n * M + k] = __float2half(W[i]);
}

// ---------------- detect dtype (block 0) + zero degree array ---------------
__global__ void k_detect_zero(const unsigned* __restrict__ p) {
    int i = blockIdx.x * blockDim.x + threadIdx.x;
    if (i < NN) g_deg[i] = 0;
    if (blockIdx.x == 0) {
        __shared__ unsigned acc;
        if (threadIdx.x == 0) acc = 0u;
        __syncthreads();
        if (threadIdx.x < 128) {
            unsigned v = p[threadIdx.x * 2 + 1];
            if (v) atomicOr(&acc, 1u);
        }
        __syncthreads();
        if (threadIdx.x == 0) g_is64 = (acc == 0u) ? 1 : 0;
    }
}

// ---------------- build src/dst with self loops + degree count -------------
__global__ void k_build_count(const void* __restrict__ ei) {
    int i = blockIdx.x * blockDim.x + threadIdx.x;
    if (i >= NE) return;
    int s, d;
    if (i < EE) {
        if (g_is64) {
            const long long* p = (const long long*)ei;
            s = (int)p[i];
            d = (int)p[EE + i];
        } else {
            const int* p = (const int*)ei;
            s = p[i];
            d = p[EE + i];
        }
    } else {
        s = d = i - EE;
    }
    g_src[i] = s;
    g_dst[i] = d;
    atomicAdd(&g_deg[d], 1);
}

// ---------------- 3-phase multi-block exclusive scan -----------------------
__global__ void k_scan1() {
    __shared__ int sm[SCAN_CH];
    int b = blockIdx.x, t = threadIdx.x;
    int i = b * SCAN_CH + t;
    int v = (i < NN) ? g_deg[i] : 0;
    sm[t] = v;
    __syncthreads();
#pragma unroll
    for (int off = 1; off < SCAN_CH; off <<= 1) {
        int u = (t >= off) ? sm[t - off] : 0;
        __syncthreads();
        sm[t] += u;
        __syncthreads();
    }
    if (i < NN) g_off[i] = sm[t] - v;
    if (t == SCAN_CH - 1) g_bsum[b] = sm[t];
}

__global__ void k_scan2() {
    __shared__ int sm[256];
    int t = threadIdx.x;
    int v = (t < SCAN_NB) ? g_bsum[t] : 0;
    sm[t] = v;
    __syncthreads();
#pragma unroll
    for (int off = 1; off < 256; off <<= 1) {
        int u = (t >= off) ? sm[t - off] : 0;
        __syncthreads();
        sm[t] += u;
        __syncthreads();
    }
    if (t < SCAN_NB) g_bsum[t] = sm[t] - v;
    if (t == 255) g_off[NN] = sm[255];
}

__global__ void k_scan3() {
    int i = blockIdx.x * blockDim.x + threadIdx.x;
    if (i >= NN) return;
    int o = g_off[i] + g_bsum[i >> 8];
    g_off[i] = o;
    g_cur[i] = o;
}

__global__ void k_scatter() {
    int i = blockIdx.x * blockDim.x + threadIdx.x;
    if (i >= NE) return;
    int p = atomicAdd(&g_cur[g_dst[i]], 1);
    g_srcp[p] = g_src[i];
}

// ---------------- fp16 tensor-core GEMM (m16n8k16 + ldmatrix) --------------
// C = A[N,M] @ W[M,Kc] with A fp16 row-major and Wt = W^T fp16 [Kc][M].
// blockIdx.y selects (Wt0 -> C0 fp16) or (Wt1 -> C1 fp32). 128x128 tile,
// 512 threads (16 warps 4m x 4n, warp tile 32x32), K-chunk 16, 2 CTA/SM
// -> 32 resident warps/SM for latency hiding.
#define SP 24   // smem row stride in halfs; 48B row stride -> LDSM conflict-free
#define BUFB (128 * SP * 2)   // bytes per buffer

__device__ __forceinline__ void mma_f16(float* c, const unsigned* a,
                                        const unsigned* b) {
    asm volatile(
        "mma.sync.aligned.m16n8k16.row.col.f32.f16.f16.f32 "
        "{%0,%1,%2,%3}, {%4,%5,%6,%7}, {%8,%9}, {%0,%1,%2,%3};"
        : "+f"(c[0]), "+f"(c[1]), "+f"(c[2]), "+f"(c[3])
        : "r"(a[0]), "r"(a[1]), "r"(a[2]), "r"(a[3]), "r"(b[0]), "r"(b[1]));
}

__device__ __forceinline__ void ldsm_x4(unsigned& r0, unsigned& r1,
                                        unsigned& r2, unsigned& r3,
                                        unsigned addr) {
    asm volatile(
        "ldmatrix.sync.aligned.m8n8.x4.shared.b16 {%0,%1,%2,%3}, [%4];"
        : "=r"(r0), "=r"(r1), "=r"(r2), "=r"(r3) : "r"(addr));
}

__global__ __launch_bounds__(512, 2)
void k_gemm(const __half* __restrict__ A,
            const __half* __restrict__ Wt0, const __half* __restrict__ Wt1,
            __half* __restrict__ C0, float* __restrict__ C1,
            int N, int M, int Kc) {
    __shared__ __half As[2][128][SP];
    __shared__ __half Bs[2][128][SP];
    const int t = threadIdx.x;
    const int lane = t & 31, warp = t >> 5;
    const int wm = (warp >> 2) << 5;   // 0..96 (4 m-warps)
    const int wn = (warp & 3) << 5;    // 0..96 (4 n-warps)
    const int row0 = blockIdx.x * 128;
    int col0 = blockIdx.y * 128;
    const __half* Wt = Wt0;
    bool tohalf = true;
    if (col0 >= Kc) { col0 -= Kc; Wt = Wt1; tohalf = false; }

    float acc[2][4][4];
#pragma unroll
    for (int mt = 0; mt < 2; mt++)
#pragma unroll
        for (int nt = 0; nt < 4; nt++)
#pragma unroll
            for (int j = 0; j < 4; j++) acc[mt][nt][j] = 0.f;

    const int srow = t >> 2;             // 0..127 (A row / Wt row)
    const int koff = (t & 3) * 4;        // half offset within 16-k chunk
    const bool aok = (row0 + srow) < N;
    const uint2 zz = make_uint2(0, 0);

    // ldmatrix lane-address bases (buffer 0)
    const unsigned aBase = (unsigned)__cvta_generic_to_shared(
        &As[0][wm + (lane & 15)][((lane >> 4) & 1) * 8]);
    const unsigned bBase = (unsigned)__cvta_generic_to_shared(
        &Bs[0][wn + ((lane >> 4) & 1) * 8 + (lane & 7)][((lane >> 3) & 1) * 8]);

    uint2 aR, bR;
    {   // chunk 0
        aR = aok ? *(const uint2*)(A + (size_t)(row0 + srow) * M + koff) : zz;
        bR = *(const uint2*)(Wt + (size_t)(col0 + srow) * M + koff);
        *(uint2*)&As[0][srow][koff] = aR;
        *(uint2*)&Bs[0][srow][koff] = bR;
    }
    __syncthreads();

    const int nchunk = M >> 4;
    const int r = lane >> 2;
    for (int ch = 0; ch < nchunk; ch++) {
        int p = ch & 1;
        bool more = (ch + 1 < nchunk);
        if (more) {                      // issue next chunk's global loads
            int k0 = (ch + 1) << 4;
            aR = aok ? *(const uint2*)(A + (size_t)(row0 + srow) * M + k0 + koff)
                     : zz;
            bR = *(const uint2*)(Wt + (size_t)(col0 + srow) * M + k0 + koff);
        }
        // fragment loads via ldmatrix (2x A, 2x B), then 8 mmas
        unsigned a[2][4], b[4][2];
#pragma unroll
        for (int mt = 0; mt < 2; mt++)
            ldsm_x4(a[mt][0], a[mt][1], a[mt][2], a[mt][3],
                    aBase + p * BUFB + mt * 16 * SP * 2);
#pragma unroll
        for (int q = 0; q < 2; q++)
            ldsm_x4(b[2 * q][0], b[2 * q][1], b[2 * q + 1][0], b[2 * q + 1][1],
                    bBase + p * BUFB + q * 16 * SP * 2);
#pragma unroll
        for (int mt = 0; mt < 2; mt++)
#pragma unroll
            for (int nt = 0; nt < 4; nt++)
                mma_f16(acc[mt][nt], a[mt], b[nt]);
        if (more) {
            int np = p ^ 1;
            *(uint2*)&As[np][srow][koff] = aR;
            *(uint2*)&Bs[np][srow][koff] = bR;
            __syncthreads();
        }
    }
    // epilogue: C0 -> fp16, C1 -> fp32
    const int c2 = (lane & 3) * 2;
#pragma unroll
    for (int mt = 0; mt < 2; mt++) {
#pragma unroll
        for (int half = 0; half < 2; half++) {
            int row = row0 + wm + mt * 16 + r + half * 8;
            if (row < N) {
#pragma unroll
                for (int nt = 0; nt < 4; nt++) {
                    float2 v = half
                        ? make_float2(acc[mt][nt][2], acc[mt][nt][3])
                        : make_float2(acc[mt][nt][0], acc[mt][nt][1]);
                    int col = col0 + wn + nt * 8 + c2;
                    if (tohalf)
                        *(__half2*)(C0 + (size_t)row * Kc + col) =
                            __floats2half2_rn(v.x, v.y);
                    else
                        *(float2*)(C1 + (size_t)row * Kc + col) = v;
                }
            }
        }
    }
}

// ---------------- fused GATv2 edge pass: logit + online softmax + agg ------
// One warp per dst node. xl gathered fp16 (8B/lane per half-row); next edge
// register-prefetched. MODE 0: bias+ELU -> fp16 h. MODE 1: head-mean -> fp32.
template<int MODE>
__global__ __launch_bounds__(256)
void k_fused(const __half* __restrict__ xl, const float* __restrict__ xr,
             const float* __restrict__ att, const float* __restrict__ bias,
             __half* __restrict__ outh, float* __restrict__ outf) {
    int n = (blockIdx.x * blockDim.x + threadIdx.x) >> 5;
    int lane = threadIdx.x & 31;
    if (n >= NN) return;
    int beg = g_off[n], end = g_off[n + 1];

    const float4* xrp = (const float4*)(xr + (size_t)n * D1);
    float4 r0 = xrp[lane], r1 = xrp[32 + lane];
    float4 atA = *(const float4*)(att + 4 * lane);
    float4 atB = *(const float4*)(att + 128 + 4 * lane);

    float mA = -1e30f, mB = -1e30f, sA = 0.f, sB = 0.f;
    float4 acc0 = make_float4(0.f, 0.f, 0.f, 0.f);
    float4 acc1 = make_float4(0.f, 0.f, 0.f, 0.f);

    int s = __ldg(&g_srcp[beg]);
    h4 h0 = *(const h4*)(xl + (size_t)s * D1 + 4 * lane);
    h4 h1 = *(const h4*)(xl + (size_t)s * D1 + 128 + 4 * lane);

    for (int i = beg; i < end; i++) {
        float2 f01 = __half22float2(h0.lo), f23 = __half22float2(h0.hi);
        float2 g01 = __half22float2(h1.lo), g23 = __half22float2(h1.hi);
        float4 cv0 = make_float4(f01.x, f01.y, f23.x, f23.y);
        float4 cv1 = make_float4(g01.x, g01.y, g23.x, g23.y);
        if (i + 1 < end) {
            int sn = __ldg(&g_srcp[i + 1]);
            h0 = *(const h4*)(xl + (size_t)sn * D1 + 4 * lane);
            h1 = *(const h4*)(xl + (size_t)sn * D1 + 128 + 4 * lane);
        }
        float z, cA, cB;
        z = cv0.x + r0.x; z = z > 0.f ? z : 0.2f * z; cA  = z * atA.x;
        z = cv0.y + r0.y; z = z > 0.f ? z : 0.2f * z; cA += z * atA.y;
        z = cv0.z + r0.z; z = z > 0.f ? z : 0.2f * z; cA += z * atA.z;
        z = cv0.w + r0.w; z = z > 0.f ? z : 0.2f * z; cA += z * atA.w;
        z = cv1.x + r1.x; z = z > 0.f ? z : 0.2f * z; cB  = z * atB.x;
        z = cv1.y + r1.y; z = z > 0.f ? z : 0.2f * z; cB += z * atB.y;
        z = cv1.z + r1.z; z = z > 0.f ? z : 0.2f * z; cB += z * atB.z;
        z = cv1.w + r1.w; z = z > 0.f ? z : 0.2f * z; cB += z * atB.w;
#pragma unroll
        for (int off = 1; off < 8; off <<= 1) {
            cA += __shfl_xor_sync(0xffffffffu, cA, off);
            cB += __shfl_xor_sync(0xffffffffu, cB, off);
        }
        float mAn = fmaxf(mA, cA);
        float scA = __expf(mA - mAn);
        float pA  = __expf(cA - mAn);
        sA = sA * scA + pA;
        acc0.x = acc0.x * scA + pA * cv0.x;
        acc0.y = acc0.y * scA + pA * cv0.y;
        acc0.z = acc0.z * scA + pA * cv0.z;
        acc0.w = acc0.w * scA + pA * cv0.w;
        mA = mAn;
        float mBn = fmaxf(mB, cB);
        float scB = __expf(mB - mBn);
        float pB  = __expf(cB - mBn);
        sB = sB * scB + pB;
        acc1.x = acc1.x * scB + pB * cv1.x;
        acc1.y = acc1.y * scB + pB * cv1.y;
        acc1.z = acc1.z * scB + pB * cv1.z;
        acc1.w = acc1.w * scB + pB * cv1.w;
        mB = mBn;
    }
    float iA = 1.f / (sA + 1e-16f);
    float iB = 1.f / (sB + 1e-16f);
    acc0.x *= iA; acc0.y *= iA; acc0.z *= iA; acc0.w *= iA;
    acc1.x *= iB; acc1.y *= iB; acc1.z *= iB; acc1.w *= iB;

    if (MODE == 1) {
        float4 tv = make_float4(acc0.x + acc1.x, acc0.y + acc1.y,
                                acc0.z + acc1.z, acc0.w + acc1.w);
#pragma unroll
        for (int off = 8; off <= 16; off <<= 1) {
            tv.x += __shfl_xor_sync(0xffffffffu, tv.x, off);
            tv.y += __shfl_xor_sync(0xffffffffu, tv.y, off);
            tv.z += __shfl_xor_sync(0xffffffffu, tv.z, off);
            tv.w += __shfl_xor_sync(0xffffffffu, tv.w, off);
        }
        if (lane < 8) {
            float4 bb = *(const float4*)(bias + lane * 4);
            float4 r = make_float4(tv.x * 0.125f + bb.x, tv.y * 0.125f + bb.y,
                                   tv.z * 0.125f + bb.z, tv.w * 0.125f + bb.w);
            *(float4*)(outf + (size_t)n * 32 + lane * 4) = r;
        }
    } else {
        // fused bias + ELU, write fp16 hidden state (GEMM2's A operand)
        float4 b0 = *(const float4*)(bias + lane * 4);
        float4 b1 = *(const float4*)(bias + 128 + lane * 4);
        float4 w0, w1;
        float v;
        v = acc0.x + b0.x; w0.x = v > 0.f ? v : expm1f(v);
        v = acc0.y + b0.y; w0.y = v > 0.f ? v : expm1f(v);
        v = acc0.z + b0.z; w0.z = v > 0.f ? v : expm1f(v);
        v = acc0.w + b0.w; w0.w = v > 0.f ? v : expm1f(v);
        v = acc1.x + b1.x; w1.x = v > 0.f ? v : expm1f(v);
        v = acc1.y + b1.y; w1.y = v > 0.f ? v : expm1f(v);
        v = acc1.z + b1.z; w1.z = v > 0.f ? v : expm1f(v);
        v = acc1.w + b1.w; w1.w = v > 0.f ? v : expm1f(v);
        h4 o0, o1;
        o0.lo = __floats2half2_rn(w0.x, w0.y);
        o0.hi = __floats2half2_rn(w0.z, w0.w);
        o1.lo = __floats2half2_rn(w1.x, w1.y);
        o1.hi = __floats2half2_rn(w1.z, w1.w);
        __half* op = outh + (size_t)n * D1;
        *(h4*)(op + 4 * lane) = o0;
        *(h4*)(op + 128 + 4 * lane) = o1;
    }
}

// ---------------- launch ---------------------------------------------------
extern "C" void kernel_launch(void* const* d_in, const int* in_sizes, int n_in,
                              void* d_out, int out_size) {
    const float* x    = (const float*)d_in[0];
    const void*  ei   = d_in[1];
    const float* Wl1  = (const float*)d_in[2];
    const float* Wr1  = (const float*)d_in[3];
    const float* att1 = (const float*)d_in[4];
    const float* b1   = (const float*)d_in[5];
    const float* Wl2  = (const float*)d_in[6];
    const float* Wr2  = (const float*)d_in[7];
    const float* att2 = (const float*)d_in[8];
    const float* b2   = (const float*)d_in[9];

    __half *pxh, *phh, *pxlh, *pw1l, *pw1r, *pw2l, *pw2r;
    float* pxr;
    cudaGetSymbolAddress((void**)&pxh,  g_xh);
    cudaGetSymbolAddress((void**)&phh,  g_hh);
    cudaGetSymbolAddress((void**)&pxlh, g_xlh);
    cudaGetSymbolAddress((void**)&pxr,  g_xr);
    cudaGetSymbolAddress((void**)&pw1l, g_w1l);
    cudaGetSymbolAddress((void**)&pw1r, g_w1r);
    cudaGetSymbolAddress((void**)&pw2l, g_w2l);
    cudaGetSymbolAddress((void**)&pw2r, g_w2r);

    dim3 gg((NN + 127) / 128, 2 * D1 / 128);
    const int ab = (NN * 32 + 255) / 256;

    // fp16 converts (main stream) — GEMM1's operands
    k_xh<<<(NN * 128 / 4 + 255) / 256, 256>>>((const float4*)x, (uint2*)pxh,
                                              NN * 128 / 4);
    k_wt<<<(128 * D1 + 255) / 256, 256>>>(Wl1, pw1l, 128, D1);
    k_wt<<<(128 * D1 + 255) / 256, 256>>>(Wr1, pw1r, 128, D1);

    // fork: layer-1 GEMM runs on side stream, overlapped with graph prep
    cudaEventRecord(g_aux.e_fork, 0);
    cudaStreamWaitEvent(g_aux.s2, g_aux.e_fork, 0);
    k_gemm<<<gg, 512, 0, g_aux.s2>>>(pxh, pw1l, pw1r, pxlh, pxr, NN, 128, D1);
    cudaEventRecord(g_aux.e_join, g_aux.s2);

    // graph prep + layer-2 weight converts (main stream, under GEMM1)
    k_wt<<<(D1 * D1 + 255) / 256, 256>>>(Wl2, pw2l, D1, D1);
    k_wt<<<(D1 * D1 + 255) / 256, 256>>>(Wr2, pw2r, D1, D1);
    k_detect_zero<<<(NN + 255) / 256, 256>>>((const unsigned*)ei);
    k_build_count<<<(NE + 255) / 256, 256>>>(ei);
    k_scan1<<<SCAN_NB, SCAN_CH>>>();
    k_scan2<<<1, 256>>>();
    k_scan3<<<(NN + 255) / 256, 256>>>();
    k_scatter<<<(NE + 255) / 256, 256>>>();

    // join: fused layer 1 needs GEMM1 outputs and the CSR
    cudaStreamWaitEvent(0, g_aux.e_join, 0);
    k_fused<0><<<ab, 256>>>(pxlh, pxr, att1, b1, phh, nullptr);

    // layer 2
    k_gemm<<<gg, 512>>>(phh, pw2l, pw2r, pxlh, pxr, NN, 256, D1);
    k_fused<1><<<ab, 256>>>(pxlh, pxr, att2, b2, nullptr, (float*)d_out);
}

// round 17
// speedup vs baseline: 1.0383x; 1.0383x over previous
#include <cuda_runtime.h>
#include <cuda_fp16.h>
#include <cstdint>
#include <math.h>

#define NN 50000
#define EE 800000
#define NE 850000      // EE + NN self loops
#define D1 256         // H*DH = H*DOUT paths both 256 wide

#define SCAN_CH 256
#define SCAN_NB ((NN + SCAN_CH - 1) / SCAN_CH)   // 196

// ---------------- scratch (device globals; no allocation allowed) ----------
__device__ int    g_is64;
__device__ int    g_src[NE];
__device__ int    g_dst[NE];
__device__ int    g_srcp[NE];    // CSR (dst-grouped) order
__device__ int    g_deg[NN];
__device__ int    g_off[NN + 1];
__device__ int    g_cur[NN];
__device__ int    g_bsum[SCAN_NB];
__device__ __half g_xh [(size_t)NN * 128];  // fp16 input features (GEMM1 A)
__device__ __half g_hh [(size_t)NN * D1];   // fp16 hidden state (GEMM2 A)
__device__ __half g_xlh[(size_t)NN * D1];   // fp16 source transform (gathered)
__device__ float  g_xr [(size_t)NN * D1];   // fp32 target transform
__device__ __half g_w1l[128 * D1];          // transposed fp16 weights [n][k]
__device__ __half g_w1r[128 * D1];
__device__ __half g_w2l[D1 * D1];
__device__ __half g_w2r[D1 * D1];

struct h4 { __half2 lo, hi; };   // 4 halfs = 8 bytes

// host-side side stream + events, created once at load (no device memory)
struct AuxStreams {
    cudaStream_t s2;
    cudaEvent_t  e_fork, e_join;
    AuxStreams() {
        cudaStreamCreateWithFlags(&s2, cudaStreamNonBlocking);
        cudaEventCreateWithFlags(&e_fork, cudaEventDisableTiming);
        cudaEventCreateWithFlags(&e_join, cudaEventDisableTiming);
    }
};
static AuxStreams g_aux;

// ---------------- fp16 converts: x and transposed weights ------------------
__global__ void k_xh(const float4* __restrict__ x, uint2* __restrict__ xh,
                     int n4) {
    int i = blockIdx.x * blockDim.x + threadIdx.x;
    if (i >= n4) return;
    float4 v = x[i];
    __half2 lo = __floats2half2_rn(v.x, v.y);
    __half2 hi = __floats2half2_rn(v.z, v.w);
    xh[i] = make_uint2(*(unsigned*)&lo, *(unsigned*)&hi);
}

__global__ void k_wt(const float* __restrict__ W, __half* __restrict__ Wt,
                     int M, int Kc) {
    int i = blockIdx.x * blockDim.x + threadIdx.x;
    if (i >= M * Kc) return;
    int k = i / Kc, n = i % Kc;
    Wt[(size_t)n * M + k] = __float2half(W[i]);
}

// ---------------- detect dtype (block 0) + zero degree array ---------------
__global__ void k_detect_zero(const unsigned* __restrict__ p) {
    int i = blockIdx.x * blockDim.x + threadIdx.x;
    if (i < NN) g_deg[i] = 0;
    if (blockIdx.x == 0) {
        __shared__ unsigned acc;
        if (threadIdx.x == 0) acc = 0u;
        __syncthreads();
        if (threadIdx.x < 128) {
            unsigned v = p[threadIdx.x * 2 + 1];
            if (v) atomicOr(&acc, 1u);
        }
        __syncthreads();
        if (threadIdx.x == 0) g_is64 = (acc == 0u) ? 1 : 0;
    }
}

// ---------------- build src/dst with self loops + degree count -------------
__global__ void k_build_count(const void* __restrict__ ei) {
    int i = blockIdx.x * blockDim.x + threadIdx.x;
    if (i >= NE) return;
    int s, d;
    if (i < EE) {
        if (g_is64) {
            const long long* p = (const long long*)ei;
            s = (int)p[i];
            d = (int)p[EE + i];
        } else {
            const int* p = (const int*)ei;
            s = p[i];
            d = p[EE + i];
        }
    } else {
        s = d = i - EE;
    }
    g_src[i] = s;
    g_dst[i] = d;
    atomicAdd(&g_deg[d], 1);
}

// ---------------- 3-phase multi-block exclusive scan -----------------------
__global__ void k_scan1() {
    __shared__ int sm[SCAN_CH];
    int b = blockIdx.x, t = threadIdx.x;
    int i = b * SCAN_CH + t;
    int v = (i < NN) ? g_deg[i] : 0;
    sm[t] = v;
    __syncthreads();
#pragma unroll
    for (int off = 1; off < SCAN_CH; off <<= 1) {
        int u = (t >= off) ? sm[t - off] : 0;
        __syncthreads();
        sm[t] += u;
        __syncthreads();
    }
    if (i < NN) g_off[i] = sm[t] - v;
    if (t == SCAN_CH - 1) g_bsum[b] = sm[t];
}

__global__ void k_scan2() {
    __shared__ int sm[256];
    int t = threadIdx.x;
    int v = (t < SCAN_NB) ? g_bsum[t] : 0;
    sm[t] = v;
    __syncthreads();
#pragma unroll
    for (int off = 1; off < 256; off <<= 1) {
        int u = (t >= off) ? sm[t - off] : 0;
        __syncthreads();
        sm[t] += u;
        __syncthreads();
    }
    if (t < SCAN_NB) g_bsum[t] = sm[t] - v;
    if (t == 255) g_off[NN] = sm[255];
}

__global__ void k_scan3() {
    int i = blockIdx.x * blockDim.x + threadIdx.x;
    if (i >= NN) return;
    int o = g_off[i] + g_bsum[i >> 8];
    g_off[i] = o;
    g_cur[i] = o;
}

__global__ void k_scatter() {
    int i = blockIdx.x * blockDim.x + threadIdx.x;
    if (i >= NE) return;
    int p = atomicAdd(&g_cur[g_dst[i]], 1);
    g_srcp[p] = g_src[i];
}

// ---------------- fp16 tensor-core GEMM: cp.async 4-stage + ldmatrix -------
// C = A[N,M] @ W[M,Kc] with A fp16 row-major and Wt = W^T fp16 [Kc][M].
// blockIdx.y selects (Wt0 -> C0 fp16) or (Wt1 -> C1 fp32). 128x128 tile,
// 512 threads (16 warps 4m x 4n, warp tile 32x32), K-chunk 16, 2 CTA/SM.
// Tile fill via cp.async.cg (L2->SMEM, bypasses L1); 4-stage ring, one
// barrier per chunk (stage ch+2 write vs ch-2 compute separated by sync).
#define SP 24                     // smem row stride in halfs
#define STGB (128 * SP * 2)       // bytes per stage per matrix

#define CPA(dst, src, sz) \
    asm volatile("cp.async.cg.shared.global [%0], [%1], 16, %2;" \
                 :: "r"(dst), "l"(src), "r"(sz))
#define CPC() asm volatile("cp.async.commit_group;")
#define CPW2() asm volatile("cp.async.wait_group 2;")

__device__ __forceinline__ void mma_f16(float* c, const unsigned* a,
                                        const unsigned* b) {
    asm volatile(
        "mma.sync.aligned.m16n8k16.row.col.f32.f16.f16.f32 "
        "{%0,%1,%2,%3}, {%4,%5,%6,%7}, {%8,%9}, {%0,%1,%2,%3};"
        : "+f"(c[0]), "+f"(c[1]), "+f"(c[2]), "+f"(c[3])
        : "r"(a[0]), "r"(a[1]), "r"(a[2]), "r"(a[3]), "r"(b[0]), "r"(b[1]));
}

__device__ __forceinline__ void ldsm_x4(unsigned& r0, unsigned& r1,
                                        unsigned& r2, unsigned& r3,
                                        unsigned addr) {
    asm volatile(
        "ldmatrix.sync.aligned.m8n8.x4.shared.b16 {%0,%1,%2,%3}, [%4];"
        : "=r"(r0), "=r"(r1), "=r"(r2), "=r"(r3) : "r"(addr));
}

__global__ __launch_bounds__(512, 2)
void k_gemm(const __half* __restrict__ A,
            const __half* __restrict__ Wt0, const __half* __restrict__ Wt1,
            __half* __restrict__ C0, float* __restrict__ C1,
            int N, int M, int Kc) {
    __shared__ __half As[4][128][SP];   // 4-stage ring, 24 KB
    __shared__ __half Bs[4][128][SP];   // 24 KB
    const int t = threadIdx.x;
    const int lane = t & 31, warp = t >> 5;
    const int wm = (warp >> 2) << 5;   // 0..96 (4 m-warps)
    const int wn = (warp & 3) << 5;    // 0..96 (4 n-warps)
    const int row0 = blockIdx.x * 128;
    int col0 = blockIdx.y * 128;
    const __half* Wt = Wt0;
    bool tohalf = true;
    if (col0 >= Kc) { col0 -= Kc; Wt = Wt1; tohalf = false; }

    float acc[2][4][4];
#pragma unroll
    for (int mt = 0; mt < 2; mt++)
#pragma unroll
        for (int nt = 0; nt < 4; nt++)
#pragma unroll
            for (int j = 0; j < 4; j++) acc[mt][nt][j] = 0.f;

    // cp.async mapping: threads 0-255 fill A, 256-511 fill B; one 16B txn
    // per thread per chunk (2 txns per 16-half row).
    const int ta   = t & 255;
    const int srow = ta >> 1;            // 0..127
    const int koff = (ta & 1) * 8;       // half offset within chunk
    const bool isA = t < 256;
    const bool aok = (row0 + srow) < N;
    const __half* gbase = isA ? A  + (size_t)(row0 + srow) * M + koff
                              : Wt + (size_t)(col0 + srow) * M + koff;
    const int sz = (isA && !aok) ? 0 : 16;   // zero-fill OOB A rows
    const unsigned sbase = (unsigned)__cvta_generic_to_shared(
        isA ? &As[0][srow][koff] : &Bs[0][srow][koff]);

    // ldmatrix lane-address bases (stage 0)
    const unsigned aBase = (unsigned)__cvta_generic_to_shared(
        &As[0][wm + (lane & 15)][((lane >> 4) & 1) * 8]);
    const unsigned bBase = (unsigned)__cvta_generic_to_shared(
        &Bs[0][wn + ((lane >> 4) & 1) * 8 + (lane & 7)][((lane >> 3) & 1) * 8]);

    const int nchunk = M >> 4;           // >= 8 always
    // prologue: chunks 0 and 1 into stages 0 and 1
    CPA(sbase, gbase, sz); CPC();
    CPA(sbase + STGB, gbase + 16, sz); CPC();

    const int r = lane >> 2;
    for (int ch = 0; ch < nchunk; ch++) {
        const int st = ch & 3;
        if (ch + 2 < nchunk)
            CPA(sbase + ((ch + 2) & 3) * STGB, gbase + (ch + 2) * 16, sz);
        CPC();                           // empty groups at tail keep count
        CPW2();                          // chunk ch complete
        __syncthreads();
        unsigned a[2][4], b[4][2];
#pragma unroll
        for (int mt = 0; mt < 2; mt++)
            ldsm_x4(a[mt][0], a[mt][1], a[mt][2], a[mt][3],
                    aBase + st * STGB + mt * 16 * SP * 2);
#pragma unroll
        for (int q = 0; q < 2; q++)
            ldsm_x4(b[2 * q][0], b[2 * q][1], b[2 * q + 1][0], b[2 * q + 1][1],
                    bBase + st * STGB + q * 16 * SP * 2);
#pragma unroll
        for (int mt = 0; mt < 2; mt++)
#pragma unroll
            for (int nt = 0; nt < 4; nt++)
                mma_f16(acc[mt][nt], a[mt], b[nt]);
    }
    // epilogue: C0 -> fp16, C1 -> fp32
    const int c2 = (lane & 3) * 2;
#pragma unroll
    for (int mt = 0; mt < 2; mt++) {
#pragma unroll
        for (int half = 0; half < 2; half++) {
            int row = row0 + wm + mt * 16 + r + half * 8;
            if (row < N) {
#pragma unroll
                for (int nt = 0; nt < 4; nt++) {
                    float2 v = half
                        ? make_float2(acc[mt][nt][2], acc[mt][nt][3])
                        : make_float2(acc[mt][nt][0], acc[mt][nt][1]);
                    int col = col0 + wn + nt * 8 + c2;
                    if (tohalf)
                        *(__half2*)(C0 + (size_t)row * Kc + col) =
                            __floats2half2_rn(v.x, v.y);
                    else
                        *(float2*)(C1 + (size_t)row * Kc + col) = v;
                }
            }
        }
    }
}

// ---------------- fused GATv2 edge pass: logit + online softmax + agg ------
// One warp per dst node. xl gathered fp16 (8B/lane per half-row); next edge
// register-prefetched. MODE 0: bias+ELU -> fp16 h. MODE 1: head-mean -> fp32.
template<int MODE>
__global__ __launch_bounds__(256)
void k_fused(const __half* __restrict__ xl, const float* __restrict__ xr,
             const float* __restrict__ att, const float* __restrict__ bias,
             __half* __restrict__ outh, float* __restrict__ outf) {
    int n = (blockIdx.x * blockDim.x + threadIdx.x) >> 5;
    int lane = threadIdx.x & 31;
    if (n >= NN) return;
    int beg = g_off[n], end = g_off[n + 1];

    const float4* xrp = (const float4*)(xr + (size_t)n * D1);
    float4 r0 = xrp[lane], r1 = xrp[32 + lane];
    float4 atA = *(const float4*)(att + 4 * lane);
    float4 atB = *(const float4*)(att + 128 + 4 * lane);

    float mA = -1e30f, mB = -1e30f, sA = 0.f, sB = 0.f;
    float4 acc0 = make_float4(0.f, 0.f, 0.f, 0.f);
    float4 acc1 = make_float4(0.f, 0.f, 0.f, 0.f);

    int s = __ldg(&g_srcp[beg]);
    h4 h0 = *(const h4*)(xl + (size_t)s * D1 + 4 * lane);
    h4 h1 = *(const h4*)(xl + (size_t)s * D1 + 128 + 4 * lane);

    for (int i = beg; i < end; i++) {
        float2 f01 = __half22float2(h0.lo), f23 = __half22float2(h0.hi);
        float2 g01 = __half22float2(h1.lo), g23 = __half22float2(h1.hi);
        float4 cv0 = make_float4(f01.x, f01.y, f23.x, f23.y);
        float4 cv1 = make_float4(g01.x, g01.y, g23.x, g23.y);
        if (i + 1 < end) {
            int sn = __ldg(&g_srcp[i + 1]);
            h0 = *(const h4*)(xl + (size_t)sn * D1 + 4 * lane);
            h1 = *(const h4*)(xl + (size_t)sn * D1 + 128 + 4 * lane);
        }
        float z, cA, cB;
        z = cv0.x + r0.x; z = z > 0.f ? z : 0.2f * z; cA  = z * atA.x;
        z = cv0.y + r0.y; z = z > 0.f ? z : 0.2f * z; cA += z * atA.y;
        z = cv0.z + r0.z; z = z > 0.f ? z : 0.2f * z; cA += z * atA.z;
        z = cv0.w + r0.w; z = z > 0.f ? z : 0.2f * z; cA += z * atA.w;
        z = cv1.x + r1.x; z = z > 0.f ? z : 0.2f * z; cB  = z * atB.x;
        z = cv1.y + r1.y; z = z > 0.f ? z : 0.2f * z; cB += z * atB.y;
        z = cv1.z + r1.z; z = z > 0.f ? z : 0.2f * z; cB += z * atB.z;
        z = cv1.w + r1.w; z = z > 0.f ? z : 0.2f * z; cB += z * atB.w;
#pragma unroll
        for (int off = 1; off < 8; off <<= 1) {
            cA += __shfl_xor_sync(0xffffffffu, cA, off);
            cB += __shfl_xor_sync(0xffffffffu, cB, off);
        }
        float mAn = fmaxf(mA, cA);
        float scA = __expf(mA - mAn);
        float pA  = __expf(cA - mAn);
        sA = sA * scA + pA;
        acc0.x = acc0.x * scA + pA * cv0.x;
        acc0.y = acc0.y * scA + pA * cv0.y;
        acc0.z = acc0.z * scA + pA * cv0.z;
        acc0.w = acc0.w * scA + pA * cv0.w;
        mA = mAn;
        float mBn = fmaxf(mB, cB);
        float scB = __expf(mB - mBn);
        float pB  = __expf(cB - mBn);
        sB = sB * scB + pB;
        acc1.x = acc1.x * scB + pB * cv1.x;
        acc1.y = acc1.y * scB + pB * cv1.y;
        acc1.z = acc1.z * scB + pB * cv1.z;
        acc1.w = acc1.w * scB + pB * cv1.w;
        mB = mBn;
    }
    float iA = 1.f / (sA + 1e-16f);
    float iB = 1.f / (sB + 1e-16f);
    acc0.x *= iA; acc0.y *= iA; acc0.z *= iA; acc0.w *= iA;
    acc1.x *= iB; acc1.y *= iB; acc1.z *= iB; acc1.w *= iB;

    if (MODE == 1) {
        float4 tv = make_float4(acc0.x + acc1.x, acc0.y + acc1.y,
                                acc0.z + acc1.z, acc0.w + acc1.w);
#pragma unroll
        for (int off = 8; off <= 16; off <<= 1) {
            tv.x += __shfl_xor_sync(0xffffffffu, tv.x, off);
            tv.y += __shfl_xor_sync(0xffffffffu, tv.y, off);
            tv.z += __shfl_xor_sync(0xffffffffu, tv.z, off);
            tv.w += __shfl_xor_sync(0xffffffffu, tv.w, off);
        }
        if (lane < 8) {
            float4 bb = *(const float4*)(bias + lane * 4);
            float4 r = make_float4(tv.x * 0.125f + bb.x, tv.y * 0.125f + bb.y,
                                   tv.z * 0.125f + bb.z, tv.w * 0.125f + bb.w);
            *(float4*)(outf + (size_t)n * 32 + lane * 4) = r;
        }
    } else {
        float4 b0 = *(const float4*)(bias + lane * 4);
        float4 b1 = *(const float4*)(bias + 128 + lane * 4);
        float4 w0, w1;
        float v;
        v = acc0.x + b0.x; w0.x = v > 0.f ? v : expm1f(v);
        v = acc0.y + b0.y; w0.y = v > 0.f ? v : expm1f(v);
        v = acc0.z + b0.z; w0.z = v > 0.f ? v : expm1f(v);
        v = acc0.w + b0.w; w0.w = v > 0.f ? v : expm1f(v);
        v = acc1.x + b1.x; w1.x = v > 0.f ? v : expm1f(v);
        v = acc1.y + b1.y; w1.y = v > 0.f ? v : expm1f(v);
        v = acc1.z + b1.z; w1.z = v > 0.f ? v : expm1f(v);
        v = acc1.w + b1.w; w1.w = v > 0.f ? v : expm1f(v);
        h4 o0, o1;
        o0.lo = __floats2half2_rn(w0.x, w0.y);
        o0.hi = __floats2half2_rn(w0.z, w0.w);
        o1.lo = __floats2half2_rn(w1.x, w1.y);
        o1.hi = __floats2half2_rn(w1.z, w1.w);
        __half* op = outh + (size_t)n * D1;
        *(h4*)(op + 4 * lane) = o0;
        *(h4*)(op + 128 + 4 * lane) = o1;
    }
}

// ---------------- launch ---------------------------------------------------
extern "C" void kernel_launch(void* const* d_in, const int* in_sizes, int n_in,
                              void* d_out, int out_size) {
    const float* x    = (const float*)d_in[0];
    const void*  ei   = d_in[1];
    const float* Wl1  = (const float*)d_in[2];
    const float* Wr1  = (const float*)d_in[3];
    const float* att1 = (const float*)d_in[4];
    const float* b1   = (const float*)d_in[5];
    const float* Wl2  = (const float*)d_in[6];
    const float* Wr2  = (const float*)d_in[7];
    const float* att2 = (const float*)d_in[8];
    const float* b2   = (const float*)d_in[9];

    __half *pxh, *phh, *pxlh, *pw1l, *pw1r, *pw2l, *pw2r;
    float* pxr;
    cudaGetSymbolAddress((void**)&pxh,  g_xh);
    cudaGetSymbolAddress((void**)&phh,  g_hh);
    cudaGetSymbolAddress((void**)&pxlh, g_xlh);
    cudaGetSymbolAddress((void**)&pxr,  g_xr);
    cudaGetSymbolAddress((void**)&pw1l, g_w1l);
    cudaGetSymbolAddress((void**)&pw1r, g_w1r);
    cudaGetSymbolAddress((void**)&pw2l, g_w2l);
    cudaGetSymbolAddress((void**)&pw2r, g_w2r);

    dim3 gg((NN + 127) / 128, 2 * D1 / 128);
    const int ab = (NN * 32 + 255) / 256;

    // fp16 converts (main stream) — GEMM1's operands
    k_xh<<<(NN * 128 / 4 + 255) / 256, 256>>>((const float4*)x, (uint2*)pxh,
                                              NN * 128 / 4);
    k_wt<<<(128 * D1 + 255) / 256, 256>>>(Wl1, pw1l, 128, D1);
    k_wt<<<(128 * D1 + 255) / 256, 256>>>(Wr1, pw1r, 128, D1);

    // fork: layer-1 GEMM runs on side stream, overlapped with graph prep
    cudaEventRecord(g_aux.e_fork, 0);
    cudaStreamWaitEvent(g_aux.s2, g_aux.e_fork, 0);
    k_gemm<<<gg, 512, 0, g_aux.s2>>>(pxh, pw1l, pw1r, pxlh, pxr, NN, 128, D1);
    cudaEventRecord(g_aux.e_join, g_aux.s2);

    // graph prep + layer-2 weight converts (main stream, under GEMM1)
    k_wt<<<(D1 * D1 + 255) / 256, 256>>>(Wl2, pw2l, D1, D1);
    k_wt<<<(D1 * D1 + 255) / 256, 256>>>(Wr2, pw2r, D1, D1);
    k_detect_zero<<<(NN + 255) / 256, 256>>>((const unsigned*)ei);
    k_build_count<<<(NE + 255) / 256, 256>>>(ei);
    k_scan1<<<SCAN_NB, SCAN_CH>>>();
    k_scan2<<<1, 256>>>();
    k_scan3<<<(NN + 255) / 256, 256>>>();
    k_scatter<<<(NE + 255) / 256, 256>>>();

    // join: fused layer 1 needs GEMM1 outputs and the CSR
    cudaStreamWaitEvent(0, g_aux.e_join, 0);
    k_fused<0><<<ab, 256>>>(pxlh, pxr, att1, b1, phh, nullptr);

    // layer 2
    k_gemm<<<gg, 512>>>(phh, pw2l, pw2r, pxlh, pxr, NN, 256, D1);
    k_fused<1><<<ab, 256>>>(pxlh, pxr, att2, b2, nullptr, (float*)d_out);
}